// round 6
// baseline (speedup 1.0000x reference)
#include <cuda_runtime.h>
#include <cuda_fp16.h>
#include <cstdint>
#include <math.h>

#define BATCH 256
#define NI    1152
#define NO    10
#define DOUT  16
#define DIN   8
#define OD    160          // NO * DOUT

// ---------------- scratch ----------------
__device__ __half g_xhat[(size_t)BATCH * NI * OD];   // [b][i][od] fp16, 94.5MB

// ---------------- packed fp32x2 helpers (sm_103a) ----------------
typedef unsigned long long ull;
__device__ __forceinline__ ull pack2(float x, float y) {
    ull r; asm("mov.b64 %0, {%1, %2};" : "=l"(r) : "f"(x), "f"(y)); return r;
}
__device__ __forceinline__ float2 unpk2(ull v) {
    float2 r; asm("mov.b64 {%0, %1}, %2;" : "=f"(r.x), "=f"(r.y) : "l"(v)); return r;
}
__device__ __forceinline__ ull ffma2(ull a, ull b, ull c) {
    ull d; asm("fma.rn.f32x2 %0, %1, %2, %3;" : "=l"(d) : "l"(a), "l"(b), "l"(c)); return d;
}

// ---------------- cluster helpers ----------------
__device__ __forceinline__ void cluster_sync_() {
    asm volatile("barrier.cluster.arrive.aligned;" ::: "memory");
    asm volatile("barrier.cluster.wait.aligned;" ::: "memory");
}
__device__ __forceinline__ unsigned int smem_u32(const void* p) {
    unsigned int a;
    asm("{ .reg .u64 t; cvta.to.shared.u64 t, %1; cvt.u32.u64 %0, t; }" : "=r"(a) : "l"(p));
    return a;
}
__device__ __forceinline__ void st_remote_f32(unsigned int saddr, unsigned int peer, float v) {
    unsigned int ra;
    asm volatile("mapa.shared::cluster.u32 %0, %1, %2;" : "=r"(ra) : "r"(saddr), "r"(peer));
    asm volatile("st.shared::cluster.f32 [%0], %1;" :: "r"(ra), "f"(v) : "memory");
}

// =====================================================================
// Kernel 1: x_hat fp16. Thread owns (i, od-OCTET): 64 weight floats
// register-resident (32 packed f32x2) across 64 batches; one STG.128
// per batch. CTA = 320 thr = 16 i x 20 octets; x tile 64 b in smem.
// =====================================================================
#define K1_IT 16
#define K1_BT 64

__global__ __launch_bounds__(320) void k1_xhat(const float* __restrict__ x,
                                               const float* __restrict__ w)
{
    __shared__ ull xs2[K1_BT][K1_IT * DIN];   // (x,x) packed, 64KB

    const int i0 = blockIdx.x * K1_IT;
    const int b0 = blockIdx.y * K1_BT;
    const int tid = threadIdx.x;

    for (int u = tid; u < K1_BT * K1_IT * DIN; u += 320) {
        int bl = u >> 7, c128 = u & 127;
        float v = x[(size_t)(b0 + bl) * (NI * DIN) + (size_t)i0 * DIN + c128];
        xs2[bl][c128] = pack2(v, v);
    }

    const int il  = tid / 20;        // 0..15
    const int oct = tid % 20;        // octet: od = oct*8 .. oct*8+7
    const int i   = i0 + il;
    const int o   = oct >> 1;
    const int d0  = (oct & 1) * 8;

    // 64 contiguous weight floats -> 32 packed regs: pw[p][c] pairs d=(2p,2p+1)
    const float4* wp = (const float4*)&w[(((size_t)o * NI + i) * 16 + d0) * 8];
    float wf[64];
    #pragma unroll
    for (int k = 0; k < 16; k++) ((float4*)wf)[k] = wp[k];
    ull pw[4][8];
    #pragma unroll
    for (int p = 0; p < 4; p++)
        #pragma unroll
        for (int c = 0; c < 8; c++)
            pw[p][c] = pack2(wf[(2 * p) * 8 + c], wf[(2 * p + 1) * 8 + c]);
    __syncthreads();

    const ull* xrow0 = &xs2[0][il * 8];
    #pragma unroll 2
    for (int b = 0; b < K1_BT; b++) {
        const ull* xr = xrow0 + (size_t)b * (K1_IT * DIN);
        ull a0 = 0ull, a1 = 0ull, a2 = 0ull, a3 = 0ull;
        #pragma unroll
        for (int c = 0; c < 8; c++) {
            ull xx = xr[c];
            a0 = ffma2(pw[0][c], xx, a0);
            a1 = ffma2(pw[1][c], xx, a1);
            a2 = ffma2(pw[2][c], xx, a2);
            a3 = ffma2(pw[3][c], xx, a3);
        }
        float2 f0 = unpk2(a0), f1 = unpk2(a1), f2 = unpk2(a2), f3 = unpk2(a3);
        union { __half2 h; unsigned int u; } c0, c1, c2, c3;
        c0.h = __float22half2_rn(f0);
        c1.h = __float22half2_rn(f1);
        c2.h = __float22half2_rn(f2);
        c3.h = __float22half2_rn(f3);
        size_t base = ((size_t)(b0 + b) * NI + i) * OD + 8 * oct;
        *(uint4*)(g_xhat + base) = make_uint4(c0.u, c1.u, c2.u, c3.u);
    }
}

// =====================================================================
// Kernel 2: fused routing. Cluster of 2 CTAs = one batch; 768 threads.
// Each CTA: 576 x_hat rows in smem (336B padded rows), s0 + 2 routing
// passes from smem; 160-float partials exchanged via DSMEM.
// Register diet: only acc[10] float4 lives across the row loop; xh is
// reloaded from smem in phase 2, t re-read from smem per row.
// =====================================================================
#define K2_THREADS 768
#define NIH   576             // i-rows per CTA
#define ROWB  336             // padded row stride (21 x 16B, odd -> conflict-free)
#define NG    192             // 4-lane groups
#define NW    24              // warps

// dynamic smem layout (bytes)
#define XH_OFF   0
#define XH_SZ    (NIH * ROWB)                  // 193,536
#define S0_OFF   (XH_OFF + XH_SZ)              // [16][160] f32
#define S0_SZ    (16 * OD * 4)                 // 10,240
#define RED_OFF  (S0_OFF + S0_SZ)              // [24][4][10] float4
#define RED_SZ   (NW * 4 * NO * 16)            // 15,360
#define SLOT_OFF (RED_OFF + RED_SZ)            // [6][160] f32
#define SLOT_SZ  (6 * OD * 4)                  // 3,840
#define TS_OFF   (SLOT_OFF + SLOT_SZ)          // [160] f32
#define TS_SZ    (OD * 4)
#define K2_SMEM  (TS_OFF + TS_SZ)              // 223,616 B

__device__ __forceinline__ float squash16(float s) {
    float v = s * s;
    v += __shfl_xor_sync(0xffffffffu, v, 8);
    v += __shfl_xor_sync(0xffffffffu, v, 4);
    v += __shfl_xor_sync(0xffffffffu, v, 2);
    v += __shfl_xor_sync(0xffffffffu, v, 1);
    return s * (v / (1.0f + v)) / (sqrtf(v) + 1e-8f);
}

__global__ __cluster_dims__(2, 1, 1) __launch_bounds__(K2_THREADS, 1)
void k2_route(float* __restrict__ dout)
{
    extern __shared__ __align__(16) char sm[];
    char*  xhb  = sm + XH_OFF;
    float* s0b  = (float*)(sm + S0_OFF);
    float* redf = (float*)(sm + RED_OFF);
    float* slot = (float*)(sm + SLOT_OFF);
    float* t_s  = (float*)(sm + TS_OFF);

    const int cta = blockIdx.x;
    const int b   = cta >> 1;
    const unsigned int rank = cta & 1;
    const unsigned int peer = rank ^ 1;
    const int tid  = threadIdx.x;
    const int lane = tid & 31;
    const int warp = tid >> 5;
    const int g = tid >> 2;
    const int j = tid & 3;

    // ---- copy my 576-row slice into smem (padded rows) ----
    const __half* src = g_xhat + ((size_t)b * NI + (size_t)rank * NIH) * OD;
    #pragma unroll 5
    for (int e = tid; e < NIH * 20; e += K2_THREADS) {
        int row = e / 20, u = e % 20;
        uint4 v = *(const uint4*)(src + (size_t)e * 8);
        *(uint4*)(xhb + row * ROWB + u * 16) = v;
    }
    __syncthreads();

    // ---- s0 partial over my 576 i (first 320 threads) ----
    if (tid < 320) {
        const int q  = tid % 20;    // od octet
        const int ir = tid / 20;    // 0..15
        float a[8];
        #pragma unroll
        for (int e = 0; e < 8; e++) a[e] = 0.f;
        #pragma unroll 4
        for (int k = 0; k < NIH / 16; k++) {
            const int row = ir + 16 * k;
            uint4 v = *(const uint4*)(xhb + row * ROWB + q * 16);
            float2 p0 = __half22float2(*(__half2*)&v.x);
            float2 p1 = __half22float2(*(__half2*)&v.y);
            float2 p2 = __half22float2(*(__half2*)&v.z);
            float2 p3 = __half22float2(*(__half2*)&v.w);
            a[0] += p0.x; a[1] += p0.y; a[2] += p1.x; a[3] += p1.y;
            a[4] += p2.x; a[5] += p2.y; a[6] += p3.x; a[7] += p3.y;
        }
        #pragma unroll
        for (int e = 0; e < 8; e++) s0b[ir * OD + q * 8 + e] = a[e];
    }
    __syncthreads();

    float myval = 0.f;
    if (tid < OD) {
        #pragma unroll
        for (int r = 0; r < 16; r++) myval += s0b[r * OD + tid];
        slot[(0 * 2 + rank) * OD + tid] = myval;
        st_remote_f32(smem_u32(&slot[(0 * 2 + rank) * OD + tid]), peer, myval);
    }
    cluster_sync_();
    float out0 = 0.f;
    if (tid < OD) {
        float s = (slot[0 * OD + tid] + slot[1 * OD + tid]) * 0.1f;
        out0 = squash16(s);
        t_s[tid] = out0;
    }
    __syncthreads();

    // ---- two routing passes ----
    #pragma unroll 1
    for (int pass = 0; pass < 2; pass++) {
        float4 acc[NO];
        #pragma unroll
        for (int o = 0; o < NO; o++) acc[o] = make_float4(0.f, 0.f, 0.f, 0.f);

        #pragma unroll 1
        for (int k = 0; k < NIH / NG; k++) {
            const int row = g + NG * k;
            const char* p = xhb + row * ROWB + j * 8;

            float e[NO];
            #pragma unroll
            for (int o = 0; o < NO; o++) {
                uint2 v = *(const uint2*)(p + o * 32);
                float2 lo = __half22float2(*(__half2*)&v.x);
                float2 hi = __half22float2(*(__half2*)&v.y);
                float4 tv = *(const float4*)&t_s[o * 16 + 4 * j];
                float pd = lo.x * tv.x;
                pd = fmaf(lo.y, tv.y, pd);
                pd = fmaf(hi.x, tv.z, pd);
                pd = fmaf(hi.y, tv.w, pd);
                pd += __shfl_xor_sync(0xffffffffu, pd, 1);
                pd += __shfl_xor_sync(0xffffffffu, pd, 2);
                e[o] = pd;
            }
            float m = e[0];
            #pragma unroll
            for (int o = 1; o < NO; o++) m = fmaxf(m, e[o]);
            float sum = 0.f;
            #pragma unroll
            for (int o = 0; o < NO; o++) { e[o] = __expf(e[o] - m); sum += e[o]; }
            const float inv = 1.0f / sum;
            #pragma unroll
            for (int o = 0; o < NO; o++) {
                uint2 v = *(const uint2*)(p + o * 32);   // smem hit (reload)
                float2 lo = __half22float2(*(__half2*)&v.x);
                float2 hi = __half22float2(*(__half2*)&v.y);
                float c = e[o] * inv;
                acc[o].x = fmaf(c, lo.x, acc[o].x);
                acc[o].y = fmaf(c, lo.y, acc[o].y);
                acc[o].z = fmaf(c, hi.x, acc[o].z);
                acc[o].w = fmaf(c, hi.y, acc[o].w);
            }
        }

        // reduce acc over the 8 groups within each warp
        #pragma unroll
        for (int o = 0; o < NO; o++) {
            #pragma unroll
            for (int msk = 4; msk <= 16; msk <<= 1) {
                acc[o].x += __shfl_xor_sync(0xffffffffu, acc[o].x, msk);
                acc[o].y += __shfl_xor_sync(0xffffffffu, acc[o].y, msk);
                acc[o].z += __shfl_xor_sync(0xffffffffu, acc[o].z, msk);
                acc[o].w += __shfl_xor_sync(0xffffffffu, acc[o].w, msk);
            }
        }
        if (lane < 4) {
            float4* rw = (float4*)redf + (warp * 4 + lane) * NO;
            #pragma unroll
            for (int o = 0; o < NO; o++) rw[o] = acc[o];
        }
        __syncthreads();

        float pv = 0.f;
        if (tid < OD) {
            const int o  = tid >> 4;
            const int dl = tid & 15;
            const int jj = dl >> 2;
            const int dd = dl & 3;
            #pragma unroll
            for (int w8 = 0; w8 < NW; w8++)
                pv += redf[((w8 * 4 + jj) * NO + o) * 4 + dd];
        }
        const int ex = 1 + pass;
        if (tid < OD) {
            slot[(ex * 2 + rank) * OD + tid] = pv;
            st_remote_f32(smem_u32(&slot[(ex * 2 + rank) * OD + tid]), peer, pv);
        }
        cluster_sync_();
        if (tid < OD) {
            float s = slot[ex * 2 * OD + tid] + slot[(ex * 2 + 1) * OD + tid];
            float out = squash16(s);
            if (pass == 0) t_s[tid] = out0 + out;
            else if (rank == 0) dout[b * OD + tid] = out;
        }
        __syncthreads();
    }
}

// =====================================================================
extern "C" void kernel_launch(void* const* d_in, const int* in_sizes, int n_in,
                              void* d_out, int out_size)
{
    const float* x = (const float*)d_in[0];   // [256,1152,8]
    const float* w = (const float*)d_in[1];   // [10,1152,16,8]
    float* out = (float*)d_out;               // [256,10,16]

    cudaFuncSetAttribute(k2_route, cudaFuncAttributeMaxDynamicSharedMemorySize, K2_SMEM);

    k1_xhat<<<dim3(NI / K1_IT, BATCH / K1_BT), 320>>>(x, w);
    k2_route<<<2 * BATCH, K2_THREADS, K2_SMEM>>>(out);
}

// round 7
// speedup vs baseline: 1.7044x; 1.7044x over previous
#include <cuda_runtime.h>
#include <cuda_fp16.h>
#include <cstdint>
#include <math.h>

#define BATCH 256
#define NI    1152
#define NO    10
#define DOUT  16
#define DIN   8
#define OD    160          // NO * DOUT

// ---------------- scratch ----------------
__device__ __half g_xhat[(size_t)BATCH * NI * OD];   // [b][i][od] fp16, 94.5MB

// ---------------- packed fp32x2 helpers (sm_103a) ----------------
typedef unsigned long long ull;
__device__ __forceinline__ ull pack2(float x, float y) {
    ull r; asm("mov.b64 %0, {%1, %2};" : "=l"(r) : "f"(x), "f"(y)); return r;
}
__device__ __forceinline__ float2 unpk2(ull v) {
    float2 r; asm("mov.b64 {%0, %1}, %2;" : "=f"(r.x), "=f"(r.y) : "l"(v)); return r;
}
__device__ __forceinline__ ull ffma2(ull a, ull b, ull c) {
    ull d; asm("fma.rn.f32x2 %0, %1, %2, %3;" : "=l"(d) : "l"(a), "l"(b), "l"(c)); return d;
}

// ---------------- cluster helpers ----------------
__device__ __forceinline__ void cluster_sync_() {
    asm volatile("barrier.cluster.arrive.aligned;" ::: "memory");
    asm volatile("barrier.cluster.wait.aligned;" ::: "memory");
}
__device__ __forceinline__ unsigned int smem_u32(const void* p) {
    unsigned int a;
    asm("{ .reg .u64 t; cvta.to.shared.u64 t, %1; cvt.u32.u64 %0, t; }" : "=r"(a) : "l"(p));
    return a;
}
__device__ __forceinline__ void st_remote_f32(unsigned int saddr, unsigned int peer, float v) {
    unsigned int ra;
    asm volatile("mapa.shared::cluster.u32 %0, %1, %2;" : "=r"(ra) : "r"(saddr), "r"(peer));
    asm volatile("st.shared::cluster.f32 [%0], %1;" :: "r"(ra), "f"(v) : "memory");
}

// =====================================================================
// Kernel 1 (R6, confirmed ~22us): thread owns (i, od-octet), 64 weight
// floats register-resident across 64 batches, one STG.128 per batch.
// =====================================================================
#define K1_IT 16
#define K1_BT 64

__global__ __launch_bounds__(320) void k1_xhat(const float* __restrict__ x,
                                               const float* __restrict__ w)
{
    __shared__ ull xs2[K1_BT][K1_IT * DIN];   // (x,x) packed, 64KB

    const int i0 = blockIdx.x * K1_IT;
    const int b0 = blockIdx.y * K1_BT;
    const int tid = threadIdx.x;

    for (int u = tid; u < K1_BT * K1_IT * DIN; u += 320) {
        int bl = u >> 7, c128 = u & 127;
        float v = x[(size_t)(b0 + bl) * (NI * DIN) + (size_t)i0 * DIN + c128];
        xs2[bl][c128] = pack2(v, v);
    }

    const int il  = tid / 20;
    const int oct = tid % 20;
    const int i   = i0 + il;
    const int o   = oct >> 1;
    const int d0  = (oct & 1) * 8;

    const float4* wp = (const float4*)&w[(((size_t)o * NI + i) * 16 + d0) * 8];
    float wf[64];
    #pragma unroll
    for (int k = 0; k < 16; k++) ((float4*)wf)[k] = wp[k];
    ull pw[4][8];
    #pragma unroll
    for (int p = 0; p < 4; p++)
        #pragma unroll
        for (int c = 0; c < 8; c++)
            pw[p][c] = pack2(wf[(2 * p) * 8 + c], wf[(2 * p + 1) * 8 + c]);
    __syncthreads();

    const ull* xrow0 = &xs2[0][il * 8];
    #pragma unroll 2
    for (int b = 0; b < K1_BT; b++) {
        const ull* xr = xrow0 + (size_t)b * (K1_IT * DIN);
        ull a0 = 0ull, a1 = 0ull, a2 = 0ull, a3 = 0ull;
        #pragma unroll
        for (int c = 0; c < 8; c++) {
            ull xx = xr[c];
            a0 = ffma2(pw[0][c], xx, a0);
            a1 = ffma2(pw[1][c], xx, a1);
            a2 = ffma2(pw[2][c], xx, a2);
            a3 = ffma2(pw[3][c], xx, a3);
        }
        float2 f0 = unpk2(a0), f1 = unpk2(a1), f2 = unpk2(a2), f3 = unpk2(a3);
        union { __half2 h; unsigned int u; } c0, c1, c2, c3;
        c0.h = __float22half2_rn(f0);
        c1.h = __float22half2_rn(f1);
        c2.h = __float22half2_rn(f2);
        c3.h = __float22half2_rn(f3);
        size_t base = ((size_t)(b0 + b) * NI + i) * OD + 8 * oct;
        *(uint4*)(g_xhat + base) = make_uint4(c0.u, c1.u, c2.u, c3.u);
    }
}

// =====================================================================
// Kernel 2: fused routing, 2-CTA cluster per batch, 576 threads.
// 8-lane group per i-row: lane = (jd d-quarter, jo o-half of 5).
// t4[5], xh[5], acc[5] register-resident; ~100 regs -> 18 warps/SM.
// =====================================================================
#define K2_THREADS 576
#define NIH   576             // i-rows per CTA
#define ROWB  336             // padded row stride (21 x 16B)
#define NGRP  72              // 8-lane groups (576/8)
#define NW    18              // warps

// dynamic smem layout (bytes)
#define XH_OFF   0
#define XH_SZ    (NIH * ROWB)                  // 193,536
#define S0_OFF   (XH_OFF + XH_SZ)              // [16][160] f32
#define S0_SZ    (16 * OD * 4)                 // 10,240
#define RED_OFF  (S0_OFF + S0_SZ)              // [18][8][5] float4
#define RED_SZ   (NW * 8 * 5 * 16)             // 11,520
#define SLOT_OFF (RED_OFF + RED_SZ)            // [6][160] f32
#define SLOT_SZ  (6 * OD * 4)                  // 3,840
#define TS_OFF   (SLOT_OFF + SLOT_SZ)          // [160] f32
#define TS_SZ    (OD * 4)
#define K2_SMEM  (TS_OFF + TS_SZ)              // 219,776 B

__device__ __forceinline__ float squash16(float s) {
    float v = s * s;
    v += __shfl_xor_sync(0xffffffffu, v, 8);
    v += __shfl_xor_sync(0xffffffffu, v, 4);
    v += __shfl_xor_sync(0xffffffffu, v, 2);
    v += __shfl_xor_sync(0xffffffffu, v, 1);
    return s * (v / (1.0f + v)) / (sqrtf(v) + 1e-8f);
}

__global__ __cluster_dims__(2, 1, 1) __launch_bounds__(K2_THREADS, 1)
void k2_route(float* __restrict__ dout)
{
    extern __shared__ __align__(16) char sm[];
    char*  xhb  = sm + XH_OFF;
    float* s0b  = (float*)(sm + S0_OFF);
    float* redf = (float*)(sm + RED_OFF);
    float* slot = (float*)(sm + SLOT_OFF);
    float* t_s  = (float*)(sm + TS_OFF);

    const int cta = blockIdx.x;
    const int b   = cta >> 1;
    const unsigned int rank = cta & 1;
    const unsigned int peer = rank ^ 1;
    const int tid  = threadIdx.x;
    const int lane = tid & 31;
    const int warp = tid >> 5;
    const int g8   = tid >> 3;        // 8-lane group id (0..71)
    const int jd   = tid & 3;         // d-quarter
    const int jo   = (tid >> 2) & 1;  // o-half: o = jo*5 + ol

    // ---- copy my 576-row slice into smem (padded rows) ----
    const __half* src = g_xhat + ((size_t)b * NI + (size_t)rank * NIH) * OD;
    #pragma unroll 5
    for (int e = tid; e < NIH * 20; e += K2_THREADS) {
        int row = e / 20, u = e % 20;
        uint4 v = *(const uint4*)(src + (size_t)e * 8);
        *(uint4*)(xhb + row * ROWB + u * 16) = v;
    }
    __syncthreads();

    // ---- s0 partial over my 576 i (first 320 threads) ----
    if (tid < 320) {
        const int q  = tid % 20;    // od octet
        const int ir = tid / 20;    // 0..15
        float a[8];
        #pragma unroll
        for (int e = 0; e < 8; e++) a[e] = 0.f;
        #pragma unroll 4
        for (int k = 0; k < NIH / 16; k++) {
            const int row = ir + 16 * k;
            uint4 v = *(const uint4*)(xhb + row * ROWB + q * 16);
            float2 p0 = __half22float2(*(__half2*)&v.x);
            float2 p1 = __half22float2(*(__half2*)&v.y);
            float2 p2 = __half22float2(*(__half2*)&v.z);
            float2 p3 = __half22float2(*(__half2*)&v.w);
            a[0] += p0.x; a[1] += p0.y; a[2] += p1.x; a[3] += p1.y;
            a[4] += p2.x; a[5] += p2.y; a[6] += p3.x; a[7] += p3.y;
        }
        #pragma unroll
        for (int e = 0; e < 8; e++) s0b[ir * OD + q * 8 + e] = a[e];
    }
    __syncthreads();

    float myval = 0.f;
    if (tid < OD) {
        #pragma unroll
        for (int r = 0; r < 16; r++) myval += s0b[r * OD + tid];
        slot[(0 * 2 + rank) * OD + tid] = myval;
        st_remote_f32(smem_u32(&slot[(0 * 2 + rank) * OD + tid]), peer, myval);
    }
    cluster_sync_();
    float out0 = 0.f;
    if (tid < OD) {
        float s = (slot[0 * OD + tid] + slot[1 * OD + tid]) * 0.1f;
        out0 = squash16(s);
        t_s[tid] = out0;
    }
    __syncthreads();

    // ---- two routing passes ----
    #pragma unroll 1
    for (int pass = 0; pass < 2; pass++) {
        float4 t4[5];
        #pragma unroll
        for (int ol = 0; ol < 5; ol++)
            t4[ol] = *(const float4*)&t_s[(jo * 5 + ol) * 16 + 4 * jd];

        float4 acc[5];
        #pragma unroll
        for (int ol = 0; ol < 5; ol++) acc[ol] = make_float4(0.f, 0.f, 0.f, 0.f);

        #pragma unroll 1
        for (int k = 0; k < NIH / NGRP; k++) {
            const int row = g8 + NGRP * k;
            const char* p = xhb + row * ROWB + jd * 8 + jo * (5 * 32);

            float4 xh[5];
            float e[5];
            #pragma unroll
            for (int ol = 0; ol < 5; ol++) {
                uint2 v = *(const uint2*)(p + ol * 32);
                float2 lo = __half22float2(*(__half2*)&v.x);
                float2 hi = __half22float2(*(__half2*)&v.y);
                xh[ol] = make_float4(lo.x, lo.y, hi.x, hi.y);
                float pd = xh[ol].x * t4[ol].x;
                pd = fmaf(xh[ol].y, t4[ol].y, pd);
                pd = fmaf(xh[ol].z, t4[ol].z, pd);
                pd = fmaf(xh[ol].w, t4[ol].w, pd);
                pd += __shfl_xor_sync(0xffffffffu, pd, 1);
                pd += __shfl_xor_sync(0xffffffffu, pd, 2);
                e[ol] = pd;
            }
            float m = e[0];
            #pragma unroll
            for (int ol = 1; ol < 5; ol++) m = fmaxf(m, e[ol]);
            m = fmaxf(m, __shfl_xor_sync(0xffffffffu, m, 4));
            float sum = 0.f;
            #pragma unroll
            for (int ol = 0; ol < 5; ol++) { e[ol] = __expf(e[ol] - m); sum += e[ol]; }
            sum += __shfl_xor_sync(0xffffffffu, sum, 4);
            const float inv = 1.0f / sum;
            #pragma unroll
            for (int ol = 0; ol < 5; ol++) {
                float c = e[ol] * inv;
                acc[ol].x = fmaf(c, xh[ol].x, acc[ol].x);
                acc[ol].y = fmaf(c, xh[ol].y, acc[ol].y);
                acc[ol].z = fmaf(c, xh[ol].z, acc[ol].z);
                acc[ol].w = fmaf(c, xh[ol].w, acc[ol].w);
            }
        }

        // reduce acc over the 4 groups within the warp (roles = lane&7)
        #pragma unroll
        for (int ol = 0; ol < 5; ol++) {
            #pragma unroll
            for (int msk = 8; msk <= 16; msk <<= 1) {
                acc[ol].x += __shfl_xor_sync(0xffffffffu, acc[ol].x, msk);
                acc[ol].y += __shfl_xor_sync(0xffffffffu, acc[ol].y, msk);
                acc[ol].z += __shfl_xor_sync(0xffffffffu, acc[ol].z, msk);
                acc[ol].w += __shfl_xor_sync(0xffffffffu, acc[ol].w, msk);
            }
        }
        if (lane < 8) {
            float4* rw = (float4*)redf + (warp * 8 + lane) * 5;
            #pragma unroll
            for (int ol = 0; ol < 5; ol++) rw[ol] = acc[ol];
        }
        __syncthreads();

        float pv = 0.f;
        if (tid < OD) {
            const int o   = tid >> 4;
            const int joF = (o >= 5) ? 1 : 0;
            const int olF = o - joF * 5;
            const int dl  = tid & 15;
            const int jdF = dl >> 2;
            const int dd  = dl & 3;
            #pragma unroll
            for (int w8 = 0; w8 < NW; w8++)
                pv += redf[(((w8 * 8) + (joF * 4 + jdF)) * 5 + olF) * 4 + dd];
        }
        const int ex = 1 + pass;
        if (tid < OD) {
            slot[(ex * 2 + rank) * OD + tid] = pv;
            st_remote_f32(smem_u32(&slot[(ex * 2 + rank) * OD + tid]), peer, pv);
        }
        cluster_sync_();
        if (tid < OD) {
            float s = slot[ex * 2 * OD + tid] + slot[(ex * 2 + 1) * OD + tid];
            float out = squash16(s);
            if (pass == 0) t_s[tid] = out0 + out;
            else if (rank == 0) dout[b * OD + tid] = out;
        }
        __syncthreads();
    }
}

// =====================================================================
extern "C" void kernel_launch(void* const* d_in, const int* in_sizes, int n_in,
                              void* d_out, int out_size)
{
    const float* x = (const float*)d_in[0];   // [256,1152,8]
    const float* w = (const float*)d_in[1];   // [10,1152,16,8]
    float* out = (float*)d_out;               // [256,10,16]

    cudaFuncSetAttribute(k2_route, cudaFuncAttributeMaxDynamicSharedMemorySize, K2_SMEM);

    k1_xhat<<<dim3(NI / K1_IT, BATCH / K1_BT), 320>>>(x, w);
    k2_route<<<2 * BATCH, K2_THREADS, K2_SMEM>>>(out);
}

// round 8
// speedup vs baseline: 1.8705x; 1.0975x over previous
#include <cuda_runtime.h>
#include <cuda_fp16.h>
#include <cstdint>
#include <math.h>

#define BATCH 256
#define NI    1152
#define NO    10
#define DOUT  16
#define DIN   8
#define OD    160          // NO * DOUT

// ---------------- scratch ----------------
__device__ __half g_xhat[(size_t)BATCH * NI * OD];   // [b][i][od] fp16, 94.5MB

// ---------------- packed fp32x2 helpers (sm_103a) ----------------
typedef unsigned long long ull;
__device__ __forceinline__ ull pack2(float x, float y) {
    ull r; asm("mov.b64 %0, {%1, %2};" : "=l"(r) : "f"(x), "f"(y)); return r;
}
__device__ __forceinline__ float2 unpk2(ull v) {
    float2 r; asm("mov.b64 {%0, %1}, %2;" : "=f"(r.x), "=f"(r.y) : "l"(v)); return r;
}
__device__ __forceinline__ ull ffma2(ull a, ull b, ull c) {
    ull d; asm("fma.rn.f32x2 %0, %1, %2, %3;" : "=l"(d) : "l"(a), "l"(b), "l"(c)); return d;
}

// ---------------- cluster helpers ----------------
__device__ __forceinline__ void cluster_sync_() {
    asm volatile("barrier.cluster.arrive.aligned;" ::: "memory");
    asm volatile("barrier.cluster.wait.aligned;" ::: "memory");
}
__device__ __forceinline__ unsigned int smem_u32(const void* p) {
    unsigned int a;
    asm("{ .reg .u64 t; cvta.to.shared.u64 t, %1; cvt.u32.u64 %0, t; }" : "=r"(a) : "l"(p));
    return a;
}
__device__ __forceinline__ void st_remote_f32(unsigned int saddr, unsigned int peer, float v) {
    unsigned int ra;
    asm volatile("mapa.shared::cluster.u32 %0, %1, %2;" : "=r"(ra) : "r"(saddr), "r"(peer));
    asm volatile("st.shared::cluster.f32 [%0], %1;" :: "r"(ra), "f"(v) : "memory");
}

// =====================================================================
// Kernel 1 (R6, ~22us): thread owns (i, od-octet), 64 weight floats
// register-resident across 64 batches, one STG.128 per batch.
// =====================================================================
#define K1_IT 16
#define K1_BT 64

__global__ __launch_bounds__(320) void k1_xhat(const float* __restrict__ x,
                                               const float* __restrict__ w)
{
    __shared__ ull xs2[K1_BT][K1_IT * DIN];   // (x,x) packed, 64KB

    const int i0 = blockIdx.x * K1_IT;
    const int b0 = blockIdx.y * K1_BT;
    const int tid = threadIdx.x;

    for (int u = tid; u < K1_BT * K1_IT * DIN; u += 320) {
        int bl = u >> 7, c128 = u & 127;
        float v = x[(size_t)(b0 + bl) * (NI * DIN) + (size_t)i0 * DIN + c128];
        xs2[bl][c128] = pack2(v, v);
    }

    const int il  = tid / 20;
    const int oct = tid % 20;
    const int i   = i0 + il;
    const int o   = oct >> 1;
    const int d0  = (oct & 1) * 8;

    const float4* wp = (const float4*)&w[(((size_t)o * NI + i) * 16 + d0) * 8];
    float wf[64];
    #pragma unroll
    for (int k = 0; k < 16; k++) ((float4*)wf)[k] = wp[k];
    ull pw[4][8];
    #pragma unroll
    for (int p = 0; p < 4; p++)
        #pragma unroll
        for (int c = 0; c < 8; c++)
            pw[p][c] = pack2(wf[(2 * p) * 8 + c], wf[(2 * p + 1) * 8 + c]);
    __syncthreads();

    const ull* xrow0 = &xs2[0][il * 8];
    #pragma unroll 2
    for (int b = 0; b < K1_BT; b++) {
        const ull* xr = xrow0 + (size_t)b * (K1_IT * DIN);
        ull a0 = 0ull, a1 = 0ull, a2 = 0ull, a3 = 0ull;
        #pragma unroll
        for (int c = 0; c < 8; c++) {
            ull xx = xr[c];
            a0 = ffma2(pw[0][c], xx, a0);
            a1 = ffma2(pw[1][c], xx, a1);
            a2 = ffma2(pw[2][c], xx, a2);
            a3 = ffma2(pw[3][c], xx, a3);
        }
        float2 f0 = unpk2(a0), f1 = unpk2(a1), f2 = unpk2(a2), f3 = unpk2(a3);
        union { __half2 h; unsigned int u; } c0, c1, c2, c3;
        c0.h = __float22half2_rn(f0);
        c1.h = __float22half2_rn(f1);
        c2.h = __float22half2_rn(f2);
        c3.h = __float22half2_rn(f3);
        size_t base = ((size_t)(b0 + b) * NI + i) * OD + 8 * oct;
        *(uint4*)(g_xhat + base) = make_uint4(c0.u, c1.u, c2.u, c3.u);
    }
}

// =====================================================================
// Kernel 2: fused routing, 2-CTA cluster per batch, 576 threads.
// Shfl-free passes: phase1 = per-thread (one i) half2 logit dots +
// softmax -> c[i][o] fp16 in smem; phase2 = (i-chunk, od-octet)
// weighted accumulation + smem tree reduce.
// =====================================================================
#define K2_THREADS 576
#define NIH   576             // i-rows per CTA
#define ROWB  336             // padded row stride (21 x 16B; 21 odd -> conflict-free)
#define NCH   24              // phase-2 i-chunks (24 rows each)

// dynamic smem layout (bytes) — all offsets 16B-aligned
#define XH_OFF   0
#define XH_SZ    (NIH * ROWB)                  // 193,536
#define C_OFF    (XH_OFF + XH_SZ)              // [576][10] fp16
#define C_SZ     (NIH * NO * 2)                // 11,520
#define PACC_OFF (C_OFF + C_SZ)                // [24][160] f32 (also s0 [16][160])
#define PACC_SZ  (NCH * OD * 4)                // 15,360
#define SLOT_OFF (PACC_OFF + PACC_SZ)          // [6][160] f32
#define SLOT_SZ  (6 * OD * 4)                  // 3,840
#define TS_OFF   (SLOT_OFF + SLOT_SZ)          // [160] f32
#define TS_SZ    (OD * 4)                      // 640
#define TH2_OFF  (TS_OFF + TS_SZ)              // [80] half2 (t packed)
#define TH2_SZ   320
#define K2_SMEM  (TH2_OFF + TH2_SZ)            // 225,216 B

__device__ __forceinline__ float squash16(float s) {
    float v = s * s;
    v += __shfl_xor_sync(0xffffffffu, v, 8);
    v += __shfl_xor_sync(0xffffffffu, v, 4);
    v += __shfl_xor_sync(0xffffffffu, v, 2);
    v += __shfl_xor_sync(0xffffffffu, v, 1);
    return s * (v / (1.0f + v)) / (sqrtf(v) + 1e-8f);
}

__global__ __cluster_dims__(2, 1, 1) __launch_bounds__(K2_THREADS, 1)
void k2_route(float* __restrict__ dout)
{
    extern __shared__ __align__(16) char sm[];
    char*    xhb  = sm + XH_OFF;
    __half*  cbuf = (__half*)(sm + C_OFF);
    float*   pacc = (float*)(sm + PACC_OFF);
    float*   slot = (float*)(sm + SLOT_OFF);
    float*   t_s  = (float*)(sm + TS_OFF);
    __half2* th2  = (__half2*)(sm + TH2_OFF);

    const int cta = blockIdx.x;
    const int b   = cta >> 1;
    const unsigned int rank = cta & 1;
    const unsigned int peer = rank ^ 1;
    const int tid = threadIdx.x;

    // ---- copy my 576-row slice into smem (padded rows) ----
    const __half* src = g_xhat + ((size_t)b * NI + (size_t)rank * NIH) * OD;
    #pragma unroll 5
    for (int e = tid; e < NIH * 20; e += K2_THREADS) {
        int row = e / 20, u = e % 20;
        uint4 v = *(const uint4*)(src + (size_t)e * 8);
        *(uint4*)(xhb + row * ROWB + u * 16) = v;
    }
    __syncthreads();

    // ---- s0 partial over my 576 i (320 threads; pacc as scratch) ----
    if (tid < 320) {
        const int q  = tid % 20;    // od octet
        const int ir = tid / 20;    // 0..15
        float a[8];
        #pragma unroll
        for (int e = 0; e < 8; e++) a[e] = 0.f;
        #pragma unroll 4
        for (int k = 0; k < NIH / 16; k++) {
            const int row = ir + 16 * k;
            uint4 v = *(const uint4*)(xhb + row * ROWB + q * 16);
            float2 p0 = __half22float2(*(__half2*)&v.x);
            float2 p1 = __half22float2(*(__half2*)&v.y);
            float2 p2 = __half22float2(*(__half2*)&v.z);
            float2 p3 = __half22float2(*(__half2*)&v.w);
            a[0] += p0.x; a[1] += p0.y; a[2] += p1.x; a[3] += p1.y;
            a[4] += p2.x; a[5] += p2.y; a[6] += p3.x; a[7] += p3.y;
        }
        #pragma unroll
        for (int e = 0; e < 8; e++) pacc[ir * OD + q * 8 + e] = a[e];
    }
    __syncthreads();

    float myval = 0.f;
    if (tid < OD) {
        #pragma unroll
        for (int r = 0; r < 16; r++) myval += pacc[r * OD + tid];
        slot[(0 * 2 + rank) * OD + tid] = myval;
        st_remote_f32(smem_u32(&slot[(0 * 2 + rank) * OD + tid]), peer, myval);
    }
    cluster_sync_();
    float out0 = 0.f;
    if (tid < OD) {
        float s = (slot[0 * OD + tid] + slot[1 * OD + tid]) * 0.1f;
        out0 = squash16(s);
        t_s[tid] = out0;
    }
    __syncthreads();

    // ---- two routing passes ----
    #pragma unroll 1
    for (int pass = 0; pass < 2; pass++) {
        // pack t to half2
        if (tid < 80) th2[tid] = __floats2half2_rn(t_s[2 * tid], t_s[2 * tid + 1]);
        __syncthreads();

        // ===== phase 1: thread = one i; 10 half2 dots + softmax -> c fp16
        {
            const char* row = xhb + tid * ROWB;
            float e[NO];
            #pragma unroll
            for (int o = 0; o < NO; o++) {
                uint4 xa = *(const uint4*)(row + o * 32);
                uint4 xb = *(const uint4*)(row + o * 32 + 16);
                uint4 ta = *(const uint4*)((const char*)th2 + o * 32);
                uint4 tb = *(const uint4*)((const char*)th2 + o * 32 + 16);
                __half2 acc = __hmul2(*(__half2*)&xa.x, *(__half2*)&ta.x);
                acc = __hfma2(*(__half2*)&xa.y, *(__half2*)&ta.y, acc);
                acc = __hfma2(*(__half2*)&xa.z, *(__half2*)&ta.z, acc);
                acc = __hfma2(*(__half2*)&xa.w, *(__half2*)&ta.w, acc);
                acc = __hfma2(*(__half2*)&xb.x, *(__half2*)&tb.x, acc);
                acc = __hfma2(*(__half2*)&xb.y, *(__half2*)&tb.y, acc);
                acc = __hfma2(*(__half2*)&xb.z, *(__half2*)&tb.z, acc);
                acc = __hfma2(*(__half2*)&xb.w, *(__half2*)&tb.w, acc);
                float2 f = __half22float2(acc);
                e[o] = f.x + f.y;
            }
            float m = e[0];
            #pragma unroll
            for (int o = 1; o < NO; o++) m = fmaxf(m, e[o]);
            float sum = 0.f;
            #pragma unroll
            for (int o = 0; o < NO; o++) { e[o] = __expf(e[o] - m); sum += e[o]; }
            const float inv = 1.0f / sum;
            __half2* cp = (__half2*)(cbuf + tid * NO);
            #pragma unroll
            for (int p = 0; p < 5; p++)
                cp[p] = __floats2half2_rn(e[2 * p] * inv, e[2 * p + 1] * inv);
        }
        __syncthreads();

        // ===== phase 2: thread = (chunk, octet); acc8 += c * xh
        if (tid < NCH * 20) {
            const int oct = tid % 20;
            const int ch  = tid / 20;
            const int o   = oct >> 1;
            float a[8];
            #pragma unroll
            for (int e2 = 0; e2 < 8; e2++) a[e2] = 0.f;
            #pragma unroll 4
            for (int kk = 0; kk < NIH / NCH; kk++) {
                const int row = ch * (NIH / NCH) + kk;
                uint4 v = *(const uint4*)(xhb + row * ROWB + oct * 16);
                float cf = __half2float(cbuf[row * NO + o]);
                float2 p0 = __half22float2(*(__half2*)&v.x);
                float2 p1 = __half22float2(*(__half2*)&v.y);
                float2 p2 = __half22float2(*(__half2*)&v.z);
                float2 p3 = __half22float2(*(__half2*)&v.w);
                a[0] = fmaf(cf, p0.x, a[0]); a[1] = fmaf(cf, p0.y, a[1]);
                a[2] = fmaf(cf, p1.x, a[2]); a[3] = fmaf(cf, p1.y, a[3]);
                a[4] = fmaf(cf, p2.x, a[4]); a[5] = fmaf(cf, p2.y, a[5]);
                a[6] = fmaf(cf, p3.x, a[6]); a[7] = fmaf(cf, p3.y, a[7]);
            }
            *(float4*)&pacc[ch * OD + oct * 8]     = make_float4(a[0], a[1], a[2], a[3]);
            *(float4*)&pacc[ch * OD + oct * 8 + 4] = make_float4(a[4], a[5], a[6], a[7]);
        }
        __syncthreads();

        // ===== reduce chunks + cluster exchange + squash
        float pv = 0.f;
        if (tid < OD) {
            #pragma unroll
            for (int ch = 0; ch < NCH; ch++) pv += pacc[ch * OD + tid];
        }
        const int ex = 1 + pass;
        if (tid < OD) {
            slot[(ex * 2 + rank) * OD + tid] = pv;
            st_remote_f32(smem_u32(&slot[(ex * 2 + rank) * OD + tid]), peer, pv);
        }
        cluster_sync_();
        if (tid < OD) {
            float s = slot[ex * 2 * OD + tid] + slot[(ex * 2 + 1) * OD + tid];
            float out = squash16(s);
            if (pass == 0) t_s[tid] = out0 + out;
            else if (rank == 0) dout[b * OD + tid] = out;
        }
        __syncthreads();
    }
}

// =====================================================================
extern "C" void kernel_launch(void* const* d_in, const int* in_sizes, int n_in,
                              void* d_out, int out_size)
{
    const float* x = (const float*)d_in[0];   // [256,1152,8]
    const float* w = (const float*)d_in[1];   // [10,1152,16,8]
    float* out = (float*)d_out;               // [256,10,16]

    cudaFuncSetAttribute(k2_route, cudaFuncAttributeMaxDynamicSharedMemorySize, K2_SMEM);

    k1_xhat<<<dim3(NI / K1_IT, BATCH / K1_BT), 320>>>(x, w);
    k2_route<<<2 * BATCH, K2_THREADS, K2_SMEM>>>(out);
}

// round 9
// speedup vs baseline: 1.9562x; 1.0458x over previous
#include <cuda_runtime.h>
#include <cuda_fp16.h>
#include <cstdint>
#include <math.h>

#define BATCH 256
#define NI    1152
#define NO    10
#define DOUT  16
#define DIN   8
#define OD    160          // NO * DOUT

// ---------------- scratch ----------------
__device__ __half g_xhat[(size_t)BATCH * NI * OD];   // [b][i][od] fp16, 94.5MB

// ---------------- packed fp32x2 helpers (sm_103a) ----------------
typedef unsigned long long ull;
__device__ __forceinline__ ull pack2(float x, float y) {
    ull r; asm("mov.b64 %0, {%1, %2};" : "=l"(r) : "f"(x), "f"(y)); return r;
}
__device__ __forceinline__ float2 unpk2(ull v) {
    float2 r; asm("mov.b64 {%0, %1}, %2;" : "=f"(r.x), "=f"(r.y) : "l"(v)); return r;
}
__device__ __forceinline__ ull ffma2(ull a, ull b, ull c) {
    ull d; asm("fma.rn.f32x2 %0, %1, %2, %3;" : "=l"(d) : "l"(a), "l"(b), "l"(c)); return d;
}

// ---------------- cluster helpers ----------------
__device__ __forceinline__ void cluster_sync_() {
    asm volatile("barrier.cluster.arrive.aligned;" ::: "memory");
    asm volatile("barrier.cluster.wait.aligned;" ::: "memory");
}
__device__ __forceinline__ unsigned int smem_u32(const void* p) {
    unsigned int a;
    asm("{ .reg .u64 t; cvta.to.shared.u64 t, %1; cvt.u32.u64 %0, t; }" : "=r"(a) : "l"(p));
    return a;
}
__device__ __forceinline__ void st_remote_f32(unsigned int saddr, unsigned int peer, float v) {
    unsigned int ra;
    asm volatile("mapa.shared::cluster.u32 %0, %1, %2;" : "=r"(ra) : "r"(saddr), "r"(peer));
    asm volatile("st.shared::cluster.f32 [%0], %1;" :: "r"(ra), "f"(v) : "memory");
}

// =====================================================================
// Kernel 1 (stable, ~22us): thread owns (i, od-octet), 64 weight floats
// register-resident across 64 batches, one STG.128 per batch.
// =====================================================================
#define K1_IT 16
#define K1_BT 64

__global__ __launch_bounds__(320) void k1_xhat(const float* __restrict__ x,
                                               const float* __restrict__ w)
{
    __shared__ ull xs2[K1_BT][K1_IT * DIN];   // (x,x) packed, 64KB

    const int i0 = blockIdx.x * K1_IT;
    const int b0 = blockIdx.y * K1_BT;
    const int tid = threadIdx.x;

    for (int u = tid; u < K1_BT * K1_IT * DIN; u += 320) {
        int bl = u >> 7, c128 = u & 127;
        float v = x[(size_t)(b0 + bl) * (NI * DIN) + (size_t)i0 * DIN + c128];
        xs2[bl][c128] = pack2(v, v);
    }

    const int il  = tid / 20;
    const int oct = tid % 20;
    const int i   = i0 + il;
    const int o   = oct >> 1;
    const int d0  = (oct & 1) * 8;

    const float4* wp = (const float4*)&w[(((size_t)o * NI + i) * 16 + d0) * 8];
    float wf[64];
    #pragma unroll
    for (int k = 0; k < 16; k++) ((float4*)wf)[k] = wp[k];
    ull pw[4][8];
    #pragma unroll
    for (int p = 0; p < 4; p++)
        #pragma unroll
        for (int c = 0; c < 8; c++)
            pw[p][c] = pack2(wf[(2 * p) * 8 + c], wf[(2 * p + 1) * 8 + c]);
    __syncthreads();

    const ull* xrow0 = &xs2[0][il * 8];
    #pragma unroll 2
    for (int b = 0; b < K1_BT; b++) {
        const ull* xr = xrow0 + (size_t)b * (K1_IT * DIN);
        ull a0 = 0ull, a1 = 0ull, a2 = 0ull, a3 = 0ull;
        #pragma unroll
        for (int c = 0; c < 8; c++) {
            ull xx = xr[c];
            a0 = ffma2(pw[0][c], xx, a0);
            a1 = ffma2(pw[1][c], xx, a1);
            a2 = ffma2(pw[2][c], xx, a2);
            a3 = ffma2(pw[3][c], xx, a3);
        }
        float2 f0 = unpk2(a0), f1 = unpk2(a1), f2 = unpk2(a2), f3 = unpk2(a3);
        union { __half2 h; unsigned int u; } c0, c1, c2, c3;
        c0.h = __float22half2_rn(f0);
        c1.h = __float22half2_rn(f1);
        c2.h = __float22half2_rn(f2);
        c3.h = __float22half2_rn(f3);
        size_t base = ((size_t)(b0 + b) * NI + i) * OD + 8 * oct;
        *(uint4*)(g_xhat + base) = make_uint4(c0.u, c1.u, c2.u, c3.u);
    }
}

// =====================================================================
// Kernel 2: fused routing, 4-CTA cluster per batch (288 rows/CTA),
// 384 threads/CTA, 2 CTAs/SM. Shfl-free phases; 4-way DSMEM exchange.
// =====================================================================
#define K2_THREADS 384
#define CLS   4
#define NIH   288             // i-rows per CTA
#define ROWB  336             // padded row stride (21 x 16B; odd -> conflict-free)
#define NCH   12              // s0/phase-2 i-chunks (24 rows each)

// dynamic smem layout (bytes) — all offsets 16B-aligned
#define XH_OFF   0
#define XH_SZ    (NIH * ROWB)                  // 96,768
#define C_OFF    (XH_OFF + XH_SZ)              // [288][10] fp16
#define C_SZ     (NIH * NO * 2)                // 5,760
#define PACC_OFF (C_OFF + C_SZ)                // [12][160] f32
#define PACC_SZ  (NCH * OD * 4)                // 7,680
#define SLOT_OFF (PACC_OFF + PACC_SZ)          // [4][160] f32 (one per rank)
#define SLOT_SZ  (CLS * OD * 4)                // 2,560
#define TS_OFF   (SLOT_OFF + SLOT_SZ)          // [160] f32
#define TS_SZ    (OD * 4)                      // 640
#define TH2_OFF  (TS_OFF + TS_SZ)              // [80] half2 (t packed)
#define TH2_SZ   320
#define K2_SMEM  (TH2_OFF + TH2_SZ)            // 113,728 B  (x2 = 227,456/SM)

__device__ __forceinline__ float squash16(float s) {
    float v = s * s;
    v += __shfl_xor_sync(0xffffffffu, v, 8);
    v += __shfl_xor_sync(0xffffffffu, v, 4);
    v += __shfl_xor_sync(0xffffffffu, v, 2);
    v += __shfl_xor_sync(0xffffffffu, v, 1);
    return s * (v / (1.0f + v)) / (sqrtf(v) + 1e-8f);
}

__global__ __cluster_dims__(CLS, 1, 1) __launch_bounds__(K2_THREADS, 2)
void k2_route(float* __restrict__ dout)
{
    extern __shared__ __align__(16) char sm[];
    char*    xhb  = sm + XH_OFF;
    __half*  cbuf = (__half*)(sm + C_OFF);
    float*   pacc = (float*)(sm + PACC_OFF);
    float*   slot = (float*)(sm + SLOT_OFF);
    float*   t_s  = (float*)(sm + TS_OFF);
    __half2* th2  = (__half2*)(sm + TH2_OFF);

    const int cta = blockIdx.x;
    const int b   = cta >> 2;
    const unsigned int rank = cta & 3;
    const int tid = threadIdx.x;

    // ---- copy my 288-row slice into smem (padded rows) ----
    const __half* src = g_xhat + ((size_t)b * NI + (size_t)rank * NIH) * OD;
    #pragma unroll 5
    for (int e = tid; e < NIH * 20; e += K2_THREADS) {
        int row = e / 20, u = e % 20;
        uint4 v = *(const uint4*)(src + (size_t)e * 8);
        *(uint4*)(xhb + row * ROWB + u * 16) = v;
    }
    __syncthreads();

    // ---- s0 partial over my 288 i (240 threads, 24 rows each) ----
    if (tid < NCH * 20) {
        const int oct = tid % 20;
        const int ch  = tid / 20;
        float a[8];
        #pragma unroll
        for (int e = 0; e < 8; e++) a[e] = 0.f;
        #pragma unroll 4
        for (int kk = 0; kk < NIH / NCH; kk++) {
            const int row = ch * (NIH / NCH) + kk;
            uint4 v = *(const uint4*)(xhb + row * ROWB + oct * 16);
            float2 p0 = __half22float2(*(__half2*)&v.x);
            float2 p1 = __half22float2(*(__half2*)&v.y);
            float2 p2 = __half22float2(*(__half2*)&v.z);
            float2 p3 = __half22float2(*(__half2*)&v.w);
            a[0] += p0.x; a[1] += p0.y; a[2] += p1.x; a[3] += p1.y;
            a[4] += p2.x; a[5] += p2.y; a[6] += p3.x; a[7] += p3.y;
        }
        *(float4*)&pacc[ch * OD + oct * 8]     = make_float4(a[0], a[1], a[2], a[3]);
        *(float4*)&pacc[ch * OD + oct * 8 + 4] = make_float4(a[4], a[5], a[6], a[7]);
    }
    __syncthreads();

    // ---- exchange 0: s0 ----
    if (tid < OD) {
        float pv = 0.f;
        #pragma unroll
        for (int ch = 0; ch < NCH; ch++) pv += pacc[ch * OD + tid];
        slot[rank * OD + tid] = pv;
        unsigned int sa = smem_u32(&slot[rank * OD + tid]);
        #pragma unroll
        for (int r = 1; r < CLS; r++) st_remote_f32(sa, rank ^ r, pv);
    }
    cluster_sync_();
    float out0 = 0.f;
    if (tid < OD) {
        float s = (slot[0 * OD + tid] + slot[1 * OD + tid] +
                   slot[2 * OD + tid] + slot[3 * OD + tid]) * 0.1f;
        out0 = squash16(s);
        t_s[tid] = out0;
    }
    __syncthreads();

    // ---- two routing passes ----
    #pragma unroll 1
    for (int pass = 0; pass < 2; pass++) {
        if (tid < 80) th2[tid] = __floats2half2_rn(t_s[2 * tid], t_s[2 * tid + 1]);
        __syncthreads();

        // ===== phase 1: thread = one i (288 threads); half2 dots + softmax
        if (tid < NIH) {
            const char* row = xhb + tid * ROWB;
            float e[NO];
            #pragma unroll
            for (int o = 0; o < NO; o++) {
                uint4 xa = *(const uint4*)(row + o * 32);
                uint4 xb = *(const uint4*)(row + o * 32 + 16);
                uint4 ta = *(const uint4*)((const char*)th2 + o * 32);
                uint4 tb = *(const uint4*)((const char*)th2 + o * 32 + 16);
                __half2 acc = __hmul2(*(__half2*)&xa.x, *(__half2*)&ta.x);
                acc = __hfma2(*(__half2*)&xa.y, *(__half2*)&ta.y, acc);
                acc = __hfma2(*(__half2*)&xa.z, *(__half2*)&ta.z, acc);
                acc = __hfma2(*(__half2*)&xa.w, *(__half2*)&ta.w, acc);
                acc = __hfma2(*(__half2*)&xb.x, *(__half2*)&tb.x, acc);
                acc = __hfma2(*(__half2*)&xb.y, *(__half2*)&tb.y, acc);
                acc = __hfma2(*(__half2*)&xb.z, *(__half2*)&tb.z, acc);
                acc = __hfma2(*(__half2*)&xb.w, *(__half2*)&tb.w, acc);
                float2 f = __half22float2(acc);
                e[o] = f.x + f.y;
            }
            float m = e[0];
            #pragma unroll
            for (int o = 1; o < NO; o++) m = fmaxf(m, e[o]);
            float sum = 0.f;
            #pragma unroll
            for (int o = 0; o < NO; o++) { e[o] = __expf(e[o] - m); sum += e[o]; }
            const float inv = 1.0f / sum;
            __half2* cp = (__half2*)(cbuf + tid * NO);
            #pragma unroll
            for (int p = 0; p < 5; p++)
                cp[p] = __floats2half2_rn(e[2 * p] * inv, e[2 * p + 1] * inv);
        }
        __syncthreads();

        // ===== phase 2: thread = (chunk, octet); acc8 += c * xh
        if (tid < NCH * 20) {
            const int oct = tid % 20;
            const int ch  = tid / 20;
            const int o   = oct >> 1;
            float a[8];
            #pragma unroll
            for (int e2 = 0; e2 < 8; e2++) a[e2] = 0.f;
            #pragma unroll 4
            for (int kk = 0; kk < NIH / NCH; kk++) {
                const int row = ch * (NIH / NCH) + kk;
                uint4 v = *(const uint4*)(xhb + row * ROWB + oct * 16);
                float cf = __half2float(cbuf[row * NO + o]);
                float2 p0 = __half22float2(*(__half2*)&v.x);
                float2 p1 = __half22float2(*(__half2*)&v.y);
                float2 p2 = __half22float2(*(__half2*)&v.z);
                float2 p3 = __half22float2(*(__half2*)&v.w);
                a[0] = fmaf(cf, p0.x, a[0]); a[1] = fmaf(cf, p0.y, a[1]);
                a[2] = fmaf(cf, p1.x, a[2]); a[3] = fmaf(cf, p1.y, a[3]);
                a[4] = fmaf(cf, p2.x, a[4]); a[5] = fmaf(cf, p2.y, a[5]);
                a[6] = fmaf(cf, p3.x, a[6]); a[7] = fmaf(cf, p3.y, a[7]);
            }
            *(float4*)&pacc[ch * OD + oct * 8]     = make_float4(a[0], a[1], a[2], a[3]);
            *(float4*)&pacc[ch * OD + oct * 8 + 4] = make_float4(a[4], a[5], a[6], a[7]);
        }
        __syncthreads();

        // ===== guard slot reuse, then exchange + squash
        cluster_sync_();
        if (tid < OD) {
            float pv = 0.f;
            #pragma unroll
            for (int ch = 0; ch < NCH; ch++) pv += pacc[ch * OD + tid];
            slot[rank * OD + tid] = pv;
            unsigned int sa = smem_u32(&slot[rank * OD + tid]);
            #pragma unroll
            for (int r = 1; r < CLS; r++) st_remote_f32(sa, rank ^ r, pv);
        }
        cluster_sync_();
        if (tid < OD) {
            float s = slot[0 * OD + tid] + slot[1 * OD + tid] +
                      slot[2 * OD + tid] + slot[3 * OD + tid];
            float out = squash16(s);
            if (pass == 0) t_s[tid] = out0 + out;
            else if (rank == 0) dout[b * OD + tid] = out;
        }
        __syncthreads();
    }
}

// =====================================================================
extern "C" void kernel_launch(void* const* d_in, const int* in_sizes, int n_in,
                              void* d_out, int out_size)
{
    const float* x = (const float*)d_in[0];   // [256,1152,8]
    const float* w = (const float*)d_in[1];   // [10,1152,16,8]
    float* out = (float*)d_out;               // [256,10,16]

    cudaFuncSetAttribute(k2_route, cudaFuncAttributeMaxDynamicSharedMemorySize, K2_SMEM);

    k1_xhat<<<dim3(NI / K1_IT, BATCH / K1_BT), 320>>>(x, w);
    k2_route<<<CLS * BATCH, K2_THREADS, K2_SMEM>>>(out);
}

// round 10
// speedup vs baseline: 2.0604x; 1.0533x over previous
#include <cuda_runtime.h>
#include <cuda_fp16.h>
#include <cstdint>
#include <math.h>

#define BATCH 256
#define NI    1152
#define NO    10
#define DOUT  16
#define DIN   8
#define OD    160          // NO * DOUT

// ---------------- scratch ----------------
__device__ __half g_xhat[(size_t)BATCH * NI * OD];   // [b][i][od] fp16, 94.5MB

// ---------------- packed fp32x2 helpers (sm_103a) ----------------
typedef unsigned long long ull;
__device__ __forceinline__ ull pack2(float x, float y) {
    ull r; asm("mov.b64 %0, {%1, %2};" : "=l"(r) : "f"(x), "f"(y)); return r;
}
__device__ __forceinline__ float2 unpk2(ull v) {
    float2 r; asm("mov.b64 {%0, %1}, %2;" : "=f"(r.x), "=f"(r.y) : "l"(v)); return r;
}
__device__ __forceinline__ ull ffma2(ull a, ull b, ull c) {
    ull d; asm("fma.rn.f32x2 %0, %1, %2, %3;" : "=l"(d) : "l"(a), "l"(b), "l"(c)); return d;
}

// ---------------- cluster helpers ----------------
__device__ __forceinline__ void cluster_sync_() {
    asm volatile("barrier.cluster.arrive.aligned;" ::: "memory");
    asm volatile("barrier.cluster.wait.aligned;" ::: "memory");
}
__device__ __forceinline__ unsigned int smem_u32(const void* p) {
    unsigned int a;
    asm("{ .reg .u64 t; cvta.to.shared.u64 t, %1; cvt.u32.u64 %0, t; }" : "=r"(a) : "l"(p));
    return a;
}
__device__ __forceinline__ void st_remote_f32(unsigned int saddr, unsigned int peer, float v) {
    unsigned int ra;
    asm volatile("mapa.shared::cluster.u32 %0, %1, %2;" : "=r"(ra) : "r"(saddr), "r"(peer));
    asm volatile("st.shared::cluster.f32 [%0], %1;" :: "r"(ra), "f"(v) : "memory");
}

// =====================================================================
// Kernel 1 (stable, ~21us): thread owns (i, od-octet), 64 weight floats
// register-resident across 64 batches, one STG.128 per batch.
// =====================================================================
#define K1_IT 16
#define K1_BT 64

__global__ __launch_bounds__(320) void k1_xhat(const float* __restrict__ x,
                                               const float* __restrict__ w)
{
    __shared__ ull xs2[K1_BT][K1_IT * DIN];   // (x,x) packed, 64KB

    const int i0 = blockIdx.x * K1_IT;
    const int b0 = blockIdx.y * K1_BT;
    const int tid = threadIdx.x;

    for (int u = tid; u < K1_BT * K1_IT * DIN; u += 320) {
        int bl = u >> 7, c128 = u & 127;
        float v = x[(size_t)(b0 + bl) * (NI * DIN) + (size_t)i0 * DIN + c128];
        xs2[bl][c128] = pack2(v, v);
    }

    const int il  = tid / 20;
    const int oct = tid % 20;
    const int i   = i0 + il;
    const int o   = oct >> 1;
    const int d0  = (oct & 1) * 8;

    const float4* wp = (const float4*)&w[(((size_t)o * NI + i) * 16 + d0) * 8];
    float wf[64];
    #pragma unroll
    for (int k = 0; k < 16; k++) ((float4*)wf)[k] = wp[k];
    ull pw[4][8];
    #pragma unroll
    for (int p = 0; p < 4; p++)
        #pragma unroll
        for (int c = 0; c < 8; c++)
            pw[p][c] = pack2(wf[(2 * p) * 8 + c], wf[(2 * p + 1) * 8 + c]);
    __syncthreads();

    const ull* xrow0 = &xs2[0][il * 8];
    #pragma unroll 2
    for (int b = 0; b < K1_BT; b++) {
        const ull* xr = xrow0 + (size_t)b * (K1_IT * DIN);
        ull a0 = 0ull, a1 = 0ull, a2 = 0ull, a3 = 0ull;
        #pragma unroll
        for (int c = 0; c < 8; c++) {
            ull xx = xr[c];
            a0 = ffma2(pw[0][c], xx, a0);
            a1 = ffma2(pw[1][c], xx, a1);
            a2 = ffma2(pw[2][c], xx, a2);
            a3 = ffma2(pw[3][c], xx, a3);
        }
        float2 f0 = unpk2(a0), f1 = unpk2(a1), f2 = unpk2(a2), f3 = unpk2(a3);
        union { __half2 h; unsigned int u; } c0, c1, c2, c3;
        c0.h = __float22half2_rn(f0);
        c1.h = __float22half2_rn(f1);
        c2.h = __float22half2_rn(f2);
        c3.h = __float22half2_rn(f3);
        size_t base = ((size_t)(b0 + b) * NI + i) * OD + 8 * oct;
        *(uint4*)(g_xhat + base) = make_uint4(c0.u, c1.u, c2.u, c3.u);
    }
}

// =====================================================================
// Kernel 2: fused routing, 4-CTA cluster per batch (288 rows/CTA),
// 384 threads/CTA, 2 CTAs/SM. Shfl-free; half2-accumulated reduces;
// double-buffered DSMEM exchange (one cluster sync per exchange).
// =====================================================================
#define K2_THREADS 384
#define CLS   4
#define NIH   288             // i-rows per CTA
#define ROWB  336             // padded row stride (21 x 16B)
#define NCH   9               // reduce chunks (32 rows each, 40 quads -> 360 thr)

// dynamic smem layout (bytes) — all 16B-aligned
#define XH_OFF    0
#define XH_SZ     (NIH * ROWB)                 // 96,768
#define C_OFF     (XH_OFF + XH_SZ)             // [288][10] fp16
#define C_SZ      (NIH * NO * 2)               // 5,760
#define PACC_OFF  (C_OFF + C_SZ)               // [9][160] f32
#define PACC_SZ   (NCH * OD * 4)               // 5,760
#define SLOT0_OFF (PACC_OFF + PACC_SZ)         // [4][160] f32
#define SLOT_SZ   (CLS * OD * 4)               // 2,560
#define SLOT1_OFF (SLOT0_OFF + SLOT_SZ)
#define TS_OFF    (SLOT1_OFF + SLOT_SZ)        // [160] f32
#define TS_SZ     (OD * 4)
#define TH2_OFF   (TS_OFF + TS_SZ)             // [80] half2
#define TH2_SZ    320
#define K2_SMEM   (TH2_OFF + TH2_SZ)           // 114,368 B (x2 = 228,736/SM)

__device__ __forceinline__ float squash16(float s) {
    float v = s * s;
    v += __shfl_xor_sync(0xffffffffu, v, 8);
    v += __shfl_xor_sync(0xffffffffu, v, 4);
    v += __shfl_xor_sync(0xffffffffu, v, 2);
    v += __shfl_xor_sync(0xffffffffu, v, 1);
    return s * (v / (1.0f + v)) / (sqrtf(v) + 1e-8f);
}

__global__ __cluster_dims__(CLS, 1, 1) __launch_bounds__(K2_THREADS, 2)
void k2_route(float* __restrict__ dout)
{
    extern __shared__ __align__(16) char sm[];
    char*    xhb  = sm + XH_OFF;
    __half*  cbuf = (__half*)(sm + C_OFF);
    float*   pacc = (float*)(sm + PACC_OFF);
    float*   t_s  = (float*)(sm + TS_OFF);
    __half2* th2  = (__half2*)(sm + TH2_OFF);

    const int cta = blockIdx.x;
    const int b   = cta >> 2;
    const unsigned int rank = cta & 3;
    const int tid = threadIdx.x;
    const int q   = tid % 40;     // od-quad
    const int ch  = tid / 40;     // chunk (0..8 valid)
    const int o_q = q >> 2;

    // ---- copy my 288-row slice into smem (padded rows) ----
    const __half* src = g_xhat + ((size_t)b * NI + (size_t)rank * NIH) * OD;
    #pragma unroll 5
    for (int e = tid; e < NIH * 20; e += K2_THREADS) {
        int row = e / 20, u = e % 20;
        uint4 v = *(const uint4*)(src + (size_t)e * 8);
        *(uint4*)(xhb + row * ROWB + u * 16) = v;
    }
    __syncthreads();

    // ---- s0 partial: thread = (ch, quad), 32 rows, half2 acc + flush/8
    if (tid < NCH * 40) {
        float4 fa = make_float4(0.f, 0.f, 0.f, 0.f);
        #pragma unroll
        for (int g8 = 0; g8 < 4; g8++) {
            __half2 a01 = __float2half2_rn(0.f), a23 = __float2half2_rn(0.f);
            #pragma unroll
            for (int kk = 0; kk < 8; kk++) {
                const int row = ch * 32 + g8 * 8 + kk;
                uint2 v = *(const uint2*)(xhb + row * ROWB + q * 8);
                a01 = __hadd2(a01, *(__half2*)&v.x);
                a23 = __hadd2(a23, *(__half2*)&v.y);
            }
            float2 f01 = __half22float2(a01), f23 = __half22float2(a23);
            fa.x += f01.x; fa.y += f01.y; fa.z += f23.x; fa.w += f23.y;
        }
        *(float4*)&pacc[ch * OD + q * 4] = fa;
    }
    __syncthreads();

    // ---- exchange 0 (buf0): s0 ----
    {
        float* slot = (float*)(sm + SLOT0_OFF);
        if (tid < OD) {
            float pv = 0.f;
            #pragma unroll
            for (int c2 = 0; c2 < NCH; c2++) pv += pacc[c2 * OD + tid];
            slot[rank * OD + tid] = pv;
            unsigned int sa = smem_u32(&slot[rank * OD + tid]);
            #pragma unroll
            for (int r = 1; r < CLS; r++) st_remote_f32(sa, rank ^ r, pv);
        }
        cluster_sync_();
        if (tid < OD) {
            float s = (slot[0 * OD + tid] + slot[1 * OD + tid] +
                       slot[2 * OD + tid] + slot[3 * OD + tid]) * 0.1f;
            t_s[tid] = squash16(s);
        }
    }
    __syncthreads();

    // ---- two routing passes ----
    #pragma unroll 1
    for (int pass = 0; pass < 2; pass++) {
        if (tid < 80) th2[tid] = __floats2half2_rn(t_s[2 * tid], t_s[2 * tid + 1]);
        __syncthreads();

        // ===== phase 1: thread = one i (288 threads); half2 dots + softmax
        if (tid < NIH) {
            const char* row = xhb + tid * ROWB;
            float e[NO];
            #pragma unroll
            for (int o = 0; o < NO; o++) {
                uint4 xa = *(const uint4*)(row + o * 32);
                uint4 xb = *(const uint4*)(row + o * 32 + 16);
                uint4 ta = *(const uint4*)((const char*)th2 + o * 32);
                uint4 tb = *(const uint4*)((const char*)th2 + o * 32 + 16);
                __half2 acc = __hmul2(*(__half2*)&xa.x, *(__half2*)&ta.x);
                acc = __hfma2(*(__half2*)&xa.y, *(__half2*)&ta.y, acc);
                acc = __hfma2(*(__half2*)&xa.z, *(__half2*)&ta.z, acc);
                acc = __hfma2(*(__half2*)&xa.w, *(__half2*)&ta.w, acc);
                acc = __hfma2(*(__half2*)&xb.x, *(__half2*)&tb.x, acc);
                acc = __hfma2(*(__half2*)&xb.y, *(__half2*)&tb.y, acc);
                acc = __hfma2(*(__half2*)&xb.z, *(__half2*)&tb.z, acc);
                acc = __hfma2(*(__half2*)&xb.w, *(__half2*)&tb.w, acc);
                float2 f = __half22float2(acc);
                e[o] = f.x + f.y;
            }
            float m = e[0];
            #pragma unroll
            for (int o = 1; o < NO; o++) m = fmaxf(m, e[o]);
            float sum = 0.f;
            #pragma unroll
            for (int o = 0; o < NO; o++) { e[o] = __expf(e[o] - m); sum += e[o]; }
            const float inv = 1.0f / sum;
            __half2* cp = (__half2*)(cbuf + tid * NO);
            #pragma unroll
            for (int p = 0; p < 5; p++)
                cp[p] = __floats2half2_rn(e[2 * p] * inv, e[2 * p + 1] * inv);
        }
        __syncthreads();

        // ===== phase 2: thread = (ch, quad); half2 acc of c*xh, flush/8
        if (tid < NCH * 40) {
            float4 fa = make_float4(0.f, 0.f, 0.f, 0.f);
            #pragma unroll
            for (int g8 = 0; g8 < 4; g8++) {
                __half2 a01 = __float2half2_rn(0.f), a23 = __float2half2_rn(0.f);
                #pragma unroll
                for (int kk = 0; kk < 8; kk++) {
                    const int row = ch * 32 + g8 * 8 + kk;
                    uint2 v = *(const uint2*)(xhb + row * ROWB + q * 8);
                    __half cf = cbuf[row * NO + o_q];
                    __half2 c2 = __half2half2(cf);
                    a01 = __hfma2(*(__half2*)&v.x, c2, a01);
                    a23 = __hfma2(*(__half2*)&v.y, c2, a23);
                }
                float2 f01 = __half22float2(a01), f23 = __half22float2(a23);
                fa.x += f01.x; fa.y += f01.y; fa.z += f23.x; fa.w += f23.y;
            }
            *(float4*)&pacc[ch * OD + q * 4] = fa;
        }
        __syncthreads();

        // ===== exchange (alternating buffer) + squash
        {
            float* slot = (float*)(sm + ((pass == 0) ? SLOT1_OFF : SLOT0_OFF));
            if (tid < OD) {
                float pv = 0.f;
                #pragma unroll
                for (int c2 = 0; c2 < NCH; c2++) pv += pacc[c2 * OD + tid];
                slot[rank * OD + tid] = pv;
                unsigned int sa = smem_u32(&slot[rank * OD + tid]);
                #pragma unroll
                for (int r = 1; r < CLS; r++) st_remote_f32(sa, rank ^ r, pv);
            }
            cluster_sync_();
            if (tid < OD) {
                float s = slot[0 * OD + tid] + slot[1 * OD + tid] +
                          slot[2 * OD + tid] + slot[3 * OD + tid];
                float out = squash16(s);
                if (pass == 0) t_s[tid] += out;          // t = out0 + out1
                else if (rank == 0) dout[b * OD + tid] = out;
            }
        }
        __syncthreads();
    }
}

// =====================================================================
extern "C" void kernel_launch(void* const* d_in, const int* in_sizes, int n_in,
                              void* d_out, int out_size)
{
    const float* x = (const float*)d_in[0];   // [256,1152,8]
    const float* w = (const float*)d_in[1];   // [10,1152,16,8]
    float* out = (float*)d_out;               // [256,10,16]

    cudaFuncSetAttribute(k2_route, cudaFuncAttributeMaxDynamicSharedMemorySize, K2_SMEM);

    k1_xhat<<<dim3(NI / K1_IT, BATCH / K1_BT), 320>>>(x, w);
    k2_route<<<CLS * BATCH, K2_THREADS, K2_SMEM>>>(out);
}

// round 11
// speedup vs baseline: 2.1100x; 1.0241x over previous
#include <cuda_runtime.h>
#include <cuda_fp16.h>
#include <cstdint>
#include <math.h>

#define BATCH 256
#define NI    1152
#define NO    10
#define DOUT  16
#define DIN   8
#define OD    160          // NO * DOUT

// ---------------- scratch ----------------
__device__ __half g_xhat[(size_t)BATCH * NI * OD];   // [b][i][od] fp16, 94.5MB

// ---------------- packed fp32x2 helpers (sm_103a) ----------------
typedef unsigned long long ull;
__device__ __forceinline__ ull pack2(float x, float y) {
    ull r; asm("mov.b64 %0, {%1, %2};" : "=l"(r) : "f"(x), "f"(y)); return r;
}
__device__ __forceinline__ float2 unpk2(ull v) {
    float2 r; asm("mov.b64 {%0, %1}, %2;" : "=f"(r.x), "=f"(r.y) : "l"(v)); return r;
}
__device__ __forceinline__ ull ffma2(ull a, ull b, ull c) {
    ull d; asm("fma.rn.f32x2 %0, %1, %2, %3;" : "=l"(d) : "l"(a), "l"(b), "l"(c)); return d;
}

// ---------------- cluster / async helpers ----------------
__device__ __forceinline__ void cluster_sync_() {
    asm volatile("barrier.cluster.arrive.aligned;" ::: "memory");
    asm volatile("barrier.cluster.wait.aligned;" ::: "memory");
}
__device__ __forceinline__ unsigned int smem_u32(const void* p) {
    unsigned int a;
    asm("{ .reg .u64 t; cvta.to.shared.u64 t, %1; cvt.u32.u64 %0, t; }" : "=r"(a) : "l"(p));
    return a;
}
__device__ __forceinline__ void st_remote_f32(unsigned int saddr, unsigned int peer, float v) {
    unsigned int ra;
    asm volatile("mapa.shared::cluster.u32 %0, %1, %2;" : "=r"(ra) : "r"(saddr), "r"(peer));
    asm volatile("st.shared::cluster.f32 [%0], %1;" :: "r"(ra), "f"(v) : "memory");
}
__device__ __forceinline__ void cp_async16(unsigned int sdst, const void* gsrc) {
    asm volatile("cp.async.cg.shared.global [%0], [%1], 16;" :: "r"(sdst), "l"(gsrc) : "memory");
}

// =====================================================================
// Kernel 1 (stable, ~21us): thread owns (i, od-octet), 64 weight floats
// register-resident across 64 batches, one STG.128 per batch.
// =====================================================================
#define K1_IT 16
#define K1_BT 64

__global__ __launch_bounds__(320) void k1_xhat(const float* __restrict__ x,
                                               const float* __restrict__ w)
{
    __shared__ ull xs2[K1_BT][K1_IT * DIN];   // (x,x) packed, 64KB

    const int i0 = blockIdx.x * K1_IT;
    const int b0 = blockIdx.y * K1_BT;
    const int tid = threadIdx.x;

    for (int u = tid; u < K1_BT * K1_IT * DIN; u += 320) {
        int bl = u >> 7, c128 = u & 127;
        float v = x[(size_t)(b0 + bl) * (NI * DIN) + (size_t)i0 * DIN + c128];
        xs2[bl][c128] = pack2(v, v);
    }

    const int il  = tid / 20;
    const int oct = tid % 20;
    const int i   = i0 + il;
    const int o   = oct >> 1;
    const int d0  = (oct & 1) * 8;

    const float4* wp = (const float4*)&w[(((size_t)o * NI + i) * 16 + d0) * 8];
    float wf[64];
    #pragma unroll
    for (int k = 0; k < 16; k++) ((float4*)wf)[k] = wp[k];
    ull pw[4][8];
    #pragma unroll
    for (int p = 0; p < 4; p++)
        #pragma unroll
        for (int c = 0; c < 8; c++)
            pw[p][c] = pack2(wf[(2 * p) * 8 + c], wf[(2 * p + 1) * 8 + c]);
    __syncthreads();

    const ull* xrow0 = &xs2[0][il * 8];
    #pragma unroll 2
    for (int b = 0; b < K1_BT; b++) {
        const ull* xr = xrow0 + (size_t)b * (K1_IT * DIN);
        ull a0 = 0ull, a1 = 0ull, a2 = 0ull, a3 = 0ull;
        #pragma unroll
        for (int c = 0; c < 8; c++) {
            ull xx = xr[c];
            a0 = ffma2(pw[0][c], xx, a0);
            a1 = ffma2(pw[1][c], xx, a1);
            a2 = ffma2(pw[2][c], xx, a2);
            a3 = ffma2(pw[3][c], xx, a3);
        }
        float2 f0 = unpk2(a0), f1 = unpk2(a1), f2 = unpk2(a2), f3 = unpk2(a3);
        union { __half2 h; unsigned int u; } c0, c1, c2, c3;
        c0.h = __float22half2_rn(f0);
        c1.h = __float22half2_rn(f1);
        c2.h = __float22half2_rn(f2);
        c3.h = __float22half2_rn(f3);
        size_t base = ((size_t)(b0 + b) * NI + i) * OD + 8 * oct;
        *(uint4*)(g_xhat + base) = make_uint4(c0.u, c1.u, c2.u, c3.u);
    }
}

// =====================================================================
// Kernel 2: fused routing, 4-CTA cluster per batch (288 rows/CTA),
// 384 threads/CTA, 2 CTAs/SM. cp.async copy-in; shfl-free phases;
// half2 accumulation (flush every 4 rows); double-buffered DSMEM exchange.
// =====================================================================
#define K2_THREADS 384
#define CLS   4
#define NIH   288             // i-rows per CTA
#define ROWB  336             // padded row stride (21 x 16B)
#define NCH   9               // reduce chunks (32 rows each, 40 quads -> 360 thr)

// dynamic smem layout (bytes) — all 16B-aligned
#define XH_OFF    0
#define XH_SZ     (NIH * ROWB)                 // 96,768
#define C_OFF     (XH_OFF + XH_SZ)             // [288][10] fp16
#define C_SZ      (NIH * NO * 2)               // 5,760
#define PACC_OFF  (C_OFF + C_SZ)               // [9][160] f32
#define PACC_SZ   (NCH * OD * 4)               // 5,760
#define SLOT0_OFF (PACC_OFF + PACC_SZ)         // [4][160] f32
#define SLOT_SZ   (CLS * OD * 4)               // 2,560
#define SLOT1_OFF (SLOT0_OFF + SLOT_SZ)
#define TS_OFF    (SLOT1_OFF + SLOT_SZ)        // [160] f32
#define TS_SZ     (OD * 4)
#define TH2_OFF   (TS_OFF + TS_SZ)             // [80] half2
#define TH2_SZ    320
#define K2_SMEM   (TH2_OFF + TH2_SZ)           // 114,368 B (x2 = 228,736/SM)

__device__ __forceinline__ float squash16(float s) {
    float v = s * s;
    v += __shfl_xor_sync(0xffffffffu, v, 8);
    v += __shfl_xor_sync(0xffffffffu, v, 4);
    v += __shfl_xor_sync(0xffffffffu, v, 2);
    v += __shfl_xor_sync(0xffffffffu, v, 1);
    return s * (v / (1.0f + v)) / (sqrtf(v) + 1e-8f);
}

__global__ __cluster_dims__(CLS, 1, 1) __launch_bounds__(K2_THREADS, 2)
void k2_route(float* __restrict__ dout)
{
    extern __shared__ __align__(16) char sm[];
    char*    xhb  = sm + XH_OFF;
    __half*  cbuf = (__half*)(sm + C_OFF);
    float*   pacc = (float*)(sm + PACC_OFF);
    float*   t_s  = (float*)(sm + TS_OFF);
    __half2* th2  = (__half2*)(sm + TH2_OFF);

    const int cta = blockIdx.x;
    const int b   = cta >> 2;
    const unsigned int rank = cta & 3;
    const int tid = threadIdx.x;
    const int q   = tid % 40;     // od-quad
    const int ch  = tid / 40;     // chunk (0..8 valid)
    const int o_q = q >> 2;

    // ---- async copy of my 288-row slice into smem (padded rows) ----
    {
        const __half* src = g_xhat + ((size_t)b * NI + (size_t)rank * NIH) * OD;
        const unsigned int xh_s = smem_u32(xhb);
        #pragma unroll
        for (int t = 0; t < 15; t++) {
            int e = tid + t * K2_THREADS;      // 0..5759
            int row = e / 20, u = e % 20;
            cp_async16(xh_s + row * ROWB + u * 16, src + (size_t)e * 8);
        }
        asm volatile("cp.async.commit_group;" ::: "memory");
        asm volatile("cp.async.wait_group 0;" ::: "memory");
    }
    __syncthreads();

    // ---- s0 partial: thread = (ch, quad), 32 rows, half2 acc, flush/4
    if (tid < NCH * 40) {
        float4 fa = make_float4(0.f, 0.f, 0.f, 0.f);
        #pragma unroll
        for (int g4 = 0; g4 < 8; g4++) {
            __half2 a01 = __float2half2_rn(0.f), a23 = __float2half2_rn(0.f);
            #pragma unroll
            for (int kk = 0; kk < 4; kk++) {
                const int row = ch * 32 + g4 * 4 + kk;
                uint2 v = *(const uint2*)(xhb + row * ROWB + q * 8);
                a01 = __hadd2(a01, *(__half2*)&v.x);
                a23 = __hadd2(a23, *(__half2*)&v.y);
            }
            float2 f01 = __half22float2(a01), f23 = __half22float2(a23);
            fa.x += f01.x; fa.y += f01.y; fa.z += f23.x; fa.w += f23.y;
        }
        *(float4*)&pacc[ch * OD + q * 4] = fa;
    }
    __syncthreads();

    // ---- exchange 0 (buf0): s0 ----
    {
        float* slot = (float*)(sm + SLOT0_OFF);
        if (tid < OD) {
            float pv = 0.f;
            #pragma unroll
            for (int c2 = 0; c2 < NCH; c2++) pv += pacc[c2 * OD + tid];
            slot[rank * OD + tid] = pv;
            unsigned int sa = smem_u32(&slot[rank * OD + tid]);
            #pragma unroll
            for (int r = 1; r < CLS; r++) st_remote_f32(sa, rank ^ r, pv);
        }
        cluster_sync_();
        if (tid < OD) {
            float s = (slot[0 * OD + tid] + slot[1 * OD + tid] +
                       slot[2 * OD + tid] + slot[3 * OD + tid]) * 0.1f;
            t_s[tid] = squash16(s);
        }
    }
    __syncthreads();

    // ---- two routing passes ----
    #pragma unroll 1
    for (int pass = 0; pass < 2; pass++) {
        if (tid < 80) th2[tid] = __floats2half2_rn(t_s[2 * tid], t_s[2 * tid + 1]);
        __syncthreads();

        // ===== phase 1: thread = one i (288 threads); half2 dots + softmax
        if (tid < NIH) {
            const char* row = xhb + tid * ROWB;
            float e[NO];
            #pragma unroll
            for (int o = 0; o < NO; o++) {
                uint4 xa = *(const uint4*)(row + o * 32);
                uint4 xb = *(const uint4*)(row + o * 32 + 16);
                uint4 ta = *(const uint4*)((const char*)th2 + o * 32);
                uint4 tb = *(const uint4*)((const char*)th2 + o * 32 + 16);
                __half2 acc = __hmul2(*(__half2*)&xa.x, *(__half2*)&ta.x);
                acc = __hfma2(*(__half2*)&xa.y, *(__half2*)&ta.y, acc);
                acc = __hfma2(*(__half2*)&xa.z, *(__half2*)&ta.z, acc);
                acc = __hfma2(*(__half2*)&xa.w, *(__half2*)&ta.w, acc);
                acc = __hfma2(*(__half2*)&xb.x, *(__half2*)&tb.x, acc);
                acc = __hfma2(*(__half2*)&xb.y, *(__half2*)&tb.y, acc);
                acc = __hfma2(*(__half2*)&xb.z, *(__half2*)&tb.z, acc);
                acc = __hfma2(*(__half2*)&xb.w, *(__half2*)&tb.w, acc);
                float2 f = __half22float2(acc);
                e[o] = f.x + f.y;
            }
            float m = e[0];
            #pragma unroll
            for (int o = 1; o < NO; o++) m = fmaxf(m, e[o]);
            float sum = 0.f;
            #pragma unroll
            for (int o = 0; o < NO; o++) { e[o] = __expf(e[o] - m); sum += e[o]; }
            const float inv = 1.0f / sum;
            __half2* cp = (__half2*)(cbuf + tid * NO);
            #pragma unroll
            for (int p = 0; p < 5; p++)
                cp[p] = __floats2half2_rn(e[2 * p] * inv, e[2 * p + 1] * inv);
        }
        __syncthreads();

        // ===== phase 2: thread = (ch, quad); half2 acc of c*xh, flush/4
        if (tid < NCH * 40) {
            float4 fa = make_float4(0.f, 0.f, 0.f, 0.f);
            #pragma unroll
            for (int g4 = 0; g4 < 8; g4++) {
                __half2 a01 = __float2half2_rn(0.f), a23 = __float2half2_rn(0.f);
                #pragma unroll
                for (int kk = 0; kk < 4; kk++) {
                    const int row = ch * 32 + g4 * 4 + kk;
                    uint2 v = *(const uint2*)(xhb + row * ROWB + q * 8);
                    __half2 c2 = __half2half2(cbuf[row * NO + o_q]);
                    a01 = __hfma2(*(__half2*)&v.x, c2, a01);
                    a23 = __hfma2(*(__half2*)&v.y, c2, a23);
                }
                float2 f01 = __half22float2(a01), f23 = __half22float2(a23);
                fa.x += f01.x; fa.y += f01.y; fa.z += f23.x; fa.w += f23.y;
            }
            *(float4*)&pacc[ch * OD + q * 4] = fa;
        }
        __syncthreads();

        // ===== exchange (alternating buffer) + squash
        {
            float* slot = (float*)(sm + ((pass == 0) ? SLOT1_OFF : SLOT0_OFF));
            if (tid < OD) {
                float pv = 0.f;
                #pragma unroll
                for (int c2 = 0; c2 < NCH; c2++) pv += pacc[c2 * OD + tid];
                slot[rank * OD + tid] = pv;
                unsigned int sa = smem_u32(&slot[rank * OD + tid]);
                #pragma unroll
                for (int r = 1; r < CLS; r++) st_remote_f32(sa, rank ^ r, pv);
            }
            cluster_sync_();
            if (tid < OD) {
                float s = slot[0 * OD + tid] + slot[1 * OD + tid] +
                          slot[2 * OD + tid] + slot[3 * OD + tid];
                float out = squash16(s);
                if (pass == 0) t_s[tid] += out;          // t = out0 + out1
                else if (rank == 0) dout[b * OD + tid] = out;
            }
        }
        __syncthreads();
    }
}

// =====================================================================
extern "C" void kernel_launch(void* const* d_in, const int* in_sizes, int n_in,
                              void* d_out, int out_size)
{
    const float* x = (const float*)d_in[0];   // [256,1152,8]
    const float* w = (const float*)d_in[1];   // [10,1152,16,8]
    float* out = (float*)d_out;               // [256,10,16]

    cudaFuncSetAttribute(k2_route, cudaFuncAttributeMaxDynamicSharedMemorySize, K2_SMEM);

    k1_xhat<<<dim3(NI / K1_IT, BATCH / K1_BT), 320>>>(x, w);
    k2_route<<<CLS * BATCH, K2_THREADS, K2_SMEM>>>(out);
}